// round 11
// baseline (speedup 1.0000x reference)
#include <cuda_runtime.h>
#include <cuda_bf16.h>
#include <math.h>

#define BB   128     // batch
#define TT   200     // timesteps
#define CC   40      // codes per visit
#define NCODE 2000
#define DAUX 16
#define EE   128     // embedding dim
#define GG   512     // 4*E
#define HH   256     // mlp hidden

// packed f32x2 FMA (SASS FFMA2) — only reachable via PTX
#define FMA2(d, a, b, c) \
    asm("fma.rn.f32x2 %0, %1, %2, %3;" : "=l"(d) : "l"(a), "l"(b), "l"(c))

__device__ __forceinline__ float plo(unsigned long long v) {
    return __uint_as_float((unsigned)v);
}
__device__ __forceinline__ float phi(unsigned long long v) {
    return __uint_as_float((unsigned)(v >> 32));
}
__device__ __forceinline__ unsigned long long pack2(float lo, float hi) {
    return (unsigned long long)__float_as_uint(lo) |
           ((unsigned long long)__float_as_uint(hi) << 32);
}

// fast, saturation-safe gates (MUFU ex2 + rcp; abs err ~1e-7)
__device__ __forceinline__ float fsig(float x) {
    return __fdividef(1.f, 1.f + __expf(-x));
}
__device__ __forceinline__ float ftanh(float x) {
    return fmaf(2.f, fsig(2.f * x), -1.f);
}

// ---------------- scratch (static device arrays; no runtime allocation) -----
__device__ float g_x   [TT * BB * EE];      // relu(embed), row = t*B + b
__device__ float g_xw  [TT * BB * GG];      // x @ W_x + b_lstm
__device__ float g_last[BB * EE];           // h at last valid timestep per row

// ---------------- kernel A: multi-hot embed (warp per visit, float4) --------
__global__ void __launch_bounds__(128, 8)
embed_kernel(const int* __restrict__ code,
             const float* __restrict__ aux,
             const float* __restrict__ Wlin,
             const float* __restrict__ blin) {
    int grp = threadIdx.x >> 5, lane = threadIdx.x & 31;
    int bt = blockIdx.x * 4 + grp;          // b*T + t
    int b = bt / TT, t = bt % TT;
    __shared__ int   codes[4][CC];
    __shared__ float flags[4][CC];
    __shared__ float auxs[4][DAUX];
    if (lane < CC)      codes[grp][lane]      = code[bt * CC + lane];
    if (lane + 32 < CC) codes[grp][lane + 32] = code[bt * CC + lane + 32];
    if (lane < DAUX)    auxs[grp][lane]       = aux[bt * DAUX + lane];
    __syncwarp();
    for (int c = lane; c < CC; c += 32) {
        int v = codes[grp][c];
        float f = (v > 0) ? 1.f : 0.f;
        for (int j = 0; j < c; j++)
            if (codes[grp][j] == v) f = 0.f;   // binary multi-hot: dedupe
        flags[grp][c] = f;
    }
    __syncwarp();
    float4 acc = *(const float4*)&blin[lane * 4];
    #pragma unroll 4
    for (int c = 0; c < CC; c++) {
        if (flags[grp][c] != 0.f) {            // uniform across warp
            float4 wv = *(const float4*)&Wlin[(codes[grp][c] - 1) * EE + lane * 4];
            acc.x += wv.x; acc.y += wv.y; acc.z += wv.z; acc.w += wv.w;
        }
    }
    #pragma unroll
    for (int k = 0; k < DAUX; k++) {
        float a = auxs[grp][k];
        float4 wv = *(const float4*)&Wlin[(NCODE + k) * EE + lane * 4];
        acc.x = fmaf(a, wv.x, acc.x); acc.y = fmaf(a, wv.y, acc.y);
        acc.z = fmaf(a, wv.z, acc.z); acc.w = fmaf(a, wv.w, acc.w);
    }
    float4 r;
    r.x = fmaxf(acc.x, 0.f); r.y = fmaxf(acc.y, 0.f);
    r.z = fmaxf(acc.z, 0.f); r.w = fmaxf(acc.w, 0.f);
    *(float4*)&g_x[(t * BB + b) * EE + lane * 4] = r;
}

// ---------------- kernel B: xw = x @ W_x + b_lstm  ([25600,128]@[128,512]) --
__global__ void __launch_bounds__(256, 1)
xw_kernel(const float* __restrict__ Wx, const float* __restrict__ blstm) {
    __shared__ float xs[64][68];   // [row][k]
    __shared__ float ws[64][68];   // [col][k]
    int tid = threadIdx.x;
    int row0 = blockIdx.x * 64, col0 = blockIdx.y * 64;
    int ty = tid >> 4, tx = tid & 15;   // rows: ty+16i, cols: tx+16j

    unsigned long long acc[4][4];
    #pragma unroll
    for (int i = 0; i < 4; i++)
        #pragma unroll
        for (int j = 0; j < 4; j++) acc[i][j] = 0ull;

    for (int kb = 0; kb < 128; kb += 64) {
        for (int i = tid; i < 64 * 16; i += 256) {
            int r = i >> 4, kq = i & 15;
            *(float4*)&xs[r][kq << 2] =
                *(const float4*)&g_x[(row0 + r) * EE + kb + (kq << 2)];
        }
        for (int i = tid; i < 64 * 64; i += 256) {
            int k = i >> 6, c = i & 63;
            ws[c][k] = Wx[(kb + k) * GG + col0 + c];
        }
        __syncthreads();
        #pragma unroll
        for (int k = 0; k < 64; k += 4) {
            ulonglong2 av[4], wv[4];
            #pragma unroll
            for (int i = 0; i < 4; i++)
                av[i] = *(const ulonglong2*)&xs[ty + 16 * i][k];
            #pragma unroll
            for (int j = 0; j < 4; j++)
                wv[j] = *(const ulonglong2*)&ws[tx + 16 * j][k];
            #pragma unroll
            for (int i = 0; i < 4; i++)
                #pragma unroll
                for (int j = 0; j < 4; j++) {
                    FMA2(acc[i][j], av[i].x, wv[j].x, acc[i][j]);
                    FMA2(acc[i][j], av[i].y, wv[j].y, acc[i][j]);
                }
        }
        __syncthreads();
    }
    #pragma unroll
    for (int i = 0; i < 4; i++) {
        int r = row0 + ty + 16 * i;
        #pragma unroll
        for (int j = 0; j < 4; j++) {
            int c = col0 + tx + 16 * j;
            g_xw[r * GG + c] = (plo(acc[i][j]) + phi(acc[i][j])) + blstm[c];
        }
    }
}

// ---------------- kernel C: single-CTA-per-row LSTM (no cross-CTA sync) -----
// 128 CTAs, 1 batch row each, 256 threads. Thread tid owns z columns tid and
// tid+256. W_h cols [0,256) live in registers (64 u64/thread); cols [256,512)
// live in smem, k4-interleaved float4 (conflict-free LDS.128). Recurrence is
// CTA-local: two __syncthreads per step replace all cluster machinery.
struct LstmS {
    ulonglong2 w2[32][256];   // [k4][col-256]: 4 consecutive k packed (128 KB)
    float h[EE];              // current hidden state
    float z[GG];              // z staging
};
#define LSTM_SMEM_BYTES ((int)sizeof(LstmS))

__global__ void __launch_bounds__(256, 1)
lstm_kernel(const float* __restrict__ Wh, const int* __restrict__ length) {
    extern __shared__ __align__(16) char smem_raw[];
    LstmS* S = (LstmS*)smem_raw;

    int tid = threadIdx.x;                 // 256
    int b = blockIdx.x;                    // batch row
    int col1 = tid;                        // z col in [0,256)
    int col2 = tid + 256;                  // z col in [256,512)

    // W_h col1 -> registers
    unsigned long long w_reg[64];
    #pragma unroll
    for (int j = 0; j < 64; j++)
        w_reg[j] = pack2(Wh[(2 * j) * GG + col1], Wh[(2 * j + 1) * GG + col1]);

    // W_h cols [256,512) -> smem, k4-interleaved (coalesced LDG: c consecutive)
    for (int i = tid; i < 32 * 256; i += 256) {
        int k4 = i >> 8, c = i & 255;
        ulonglong2 v;
        v.x = pack2(Wh[(4 * k4 + 0) * GG + 256 + c],
                    Wh[(4 * k4 + 1) * GG + 256 + c]);
        v.y = pack2(Wh[(4 * k4 + 2) * GG + 256 + c],
                    Wh[(4 * k4 + 3) * GG + 256 + c]);
        S->w2[k4][c] = v;
    }

    // h_0 = 0
    if (tid < EE) S->h[tid] = 0.f;

    int Lrow = length[b];
    float cst = 0.f;                       // cell state for e = tid (tid<128)

    // preload xw for t=0 (coalesced)
    float xw0 = g_xw[b * GG + col1];
    float xw1 = g_xw[b * GG + col2];
    __syncthreads();

    for (int t = 0; t < TT; t++) {
        unsigned long long a0 = 0ull, a1 = 0ull;
        #pragma unroll
        for (int k4 = 0; k4 < 32; k4++) {
            ulonglong2 hv = *(const ulonglong2*)&S->h[4 * k4];   // broadcast
            ulonglong2 wv = S->w2[k4][tid];                      // conflict-free
            FMA2(a0, hv.x, w_reg[2 * k4],     a0);
            FMA2(a1, hv.x, wv.x,              a1);
            FMA2(a0, hv.y, w_reg[2 * k4 + 1], a0);
            FMA2(a1, hv.y, wv.y,              a1);
        }
        S->z[col1] = xw0 + (plo(a0) + phi(a0));
        S->z[col2] = xw1 + (plo(a1) + phi(a1));
        __syncthreads();   // z complete; h reads of this step done

        if (tid < 128) {   // e = tid
            float zi = S->z[tid];
            float zf = S->z[128 + tid];
            float zg = S->z[256 + tid];
            float zo = S->z[384 + tid];
            cst = fsig(zf) * cst + fsig(zi) * ftanh(zg);
            float h = fsig(zo) * ftanh(cst);
            S->h[tid] = h;
            if (t + 1 == Lrow) g_last[b * EE + tid] = h;
        }

        // prefetch xw for t+1 (hidden under epilogue + sync)
        if (t + 1 < TT) {
            xw0 = g_xw[((t + 1) * BB + b) * GG + col1];
            xw1 = g_xw[((t + 1) * BB + b) * GG + col2];
        }
        __syncthreads();   // h_{t+1} ready
    }
}

// ---------------- kernel D: MLP head + L2-normalize --------------------------
__global__ void __launch_bounds__(256, 1)
head_kernel(const float* __restrict__ W0,
            const float* __restrict__ b0v,
            const float* __restrict__ W1,
            const float* __restrict__ b1v,
            float* __restrict__ out) {
    int b = blockIdx.x;             // 128
    int tid = threadIdx.x;          // 256
    __shared__ float hl[EE];
    __shared__ float m[HH];
    __shared__ float red[HH];
    if (tid < EE) hl[tid] = g_last[b * EE + tid];
    __syncthreads();
    float a0 = b0v[tid], a1 = 0.f, a2 = 0.f, a3 = 0.f;
    #pragma unroll
    for (int k = 0; k < EE; k += 4) {
        a0 = fmaf(hl[k],     W0[(k)     * HH + tid], a0);
        a1 = fmaf(hl[k + 1], W0[(k + 1) * HH + tid], a1);
        a2 = fmaf(hl[k + 2], W0[(k + 2) * HH + tid], a2);
        a3 = fmaf(hl[k + 3], W0[(k + 3) * HH + tid], a3);
    }
    m[tid] = fmaxf((a0 + a1) + (a2 + a3), 0.f);
    __syncthreads();
    float f0 = b1v[tid], f1 = 0.f, f2 = 0.f, f3 = 0.f;
    #pragma unroll
    for (int k = 0; k < HH; k += 4) {
        f0 = fmaf(m[k],     W1[(k)     * HH + tid], f0);
        f1 = fmaf(m[k + 1], W1[(k + 1) * HH + tid], f1);
        f2 = fmaf(m[k + 2], W1[(k + 2) * HH + tid], f2);
        f3 = fmaf(m[k + 3], W1[(k + 3) * HH + tid], f3);
    }
    float f = (f0 + f1) + (f2 + f3);
    red[tid] = f * f;
    __syncthreads();
    for (int s = 128; s > 0; s >>= 1) {
        if (tid < s) red[tid] += red[tid + s];
        __syncthreads();
    }
    out[b * HH + tid] = f / sqrtf(red[0]);
}

// ---------------- launch -----------------------------------------------------
extern "C" void kernel_launch(void* const* d_in, const int* in_sizes, int n_in,
                              void* d_out, int out_size) {
    const int*   code   = (const int*)  d_in[0];
    const float* aux    = (const float*)d_in[1];
    const int*   length = (const int*)  d_in[2];
    // d_in[3] = is_training (unused, inference)
    const float* Wlin   = (const float*)d_in[4];
    const float* blin   = (const float*)d_in[5];
    const float* Wx     = (const float*)d_in[6];
    const float* Wh     = (const float*)d_in[7];
    const float* blstm  = (const float*)d_in[8];
    const float* W0     = (const float*)d_in[9];
    const float* b0v    = (const float*)d_in[10];
    const float* W1     = (const float*)d_in[11];
    const float* b1v    = (const float*)d_in[12];
    float* out = (float*)d_out;

    cudaFuncSetAttribute(lstm_kernel,
                         cudaFuncAttributeMaxDynamicSharedMemorySize,
                         LSTM_SMEM_BYTES);

    embed_kernel<<<BB * TT / 4, 128>>>(code, aux, Wlin, blin);
    dim3 gb(TT * BB / 64, GG / 64);
    xw_kernel<<<gb, 256>>>(Wx, blstm);
    lstm_kernel<<<BB, 256, LSTM_SMEM_BYTES>>>(Wh, length);
    head_kernel<<<BB, 256>>>(W0, b0v, W1, b1v, out);
}

// round 12
// speedup vs baseline: 1.0458x; 1.0458x over previous
#include <cuda_runtime.h>
#include <cuda_bf16.h>
#include <math.h>

#define BB   128     // batch
#define TT   200     // timesteps
#define CC   40      // codes per visit
#define NCODE 2000
#define DAUX 16
#define EE   128     // embedding dim
#define GG   512     // 4*E
#define HH   256     // mlp hidden

// packed f32x2 FMA (SASS FFMA2) — only reachable via PTX
#define FMA2(d, a, b, c) \
    asm("fma.rn.f32x2 %0, %1, %2, %3;" : "=l"(d) : "l"(a), "l"(b), "l"(c))

__device__ __forceinline__ float plo(unsigned long long v) {
    return __uint_as_float((unsigned)v);
}
__device__ __forceinline__ float phi(unsigned long long v) {
    return __uint_as_float((unsigned)(v >> 32));
}
__device__ __forceinline__ unsigned long long pack2(float lo, float hi) {
    return (unsigned long long)__float_as_uint(lo) |
           ((unsigned long long)__float_as_uint(hi) << 32);
}

__device__ __forceinline__ unsigned smem_u32(const void* p) {
    unsigned a;
    asm("{ .reg .u64 t; cvta.to.shared.u64 t, %1; cvt.u32.u64 %0, t; }"
        : "=r"(a) : "l"(p));
    return a;
}

// fast, saturation-safe gates (MUFU ex2 + rcp; abs err ~1e-7)
__device__ __forceinline__ float fsig(float x) {
    return __fdividef(1.f, 1.f + __expf(-x));
}
__device__ __forceinline__ float ftanh(float x) {
    return fmaf(2.f, fsig(2.f * x), -1.f);
}

// mbarrier + st.async helpers
__device__ __forceinline__ void mbar_init(unsigned addr, unsigned cnt) {
    asm volatile("mbarrier.init.shared.b64 [%0], %1;" :: "r"(addr), "r"(cnt)
                 : "memory");
}
__device__ __forceinline__ void mbar_arm(unsigned addr, unsigned tx) {
    asm volatile("mbarrier.arrive.expect_tx.shared.b64 _, [%0], %1;"
                 :: "r"(addr), "r"(tx) : "memory");
}
__device__ __forceinline__ void mbar_wait(unsigned addr, unsigned parity) {
    unsigned done;
    asm volatile(
        "{\n\t.reg .pred p;\n\t"
        "mbarrier.try_wait.parity.acquire.cluster.shared::cta.b64 p, [%1], %2;\n\t"
        "selp.b32 %0, 1, 0, p;\n\t}"
        : "=r"(done) : "r"(addr), "r"(parity) : "memory");
    while (!done) {
        asm volatile(
            "{\n\t.reg .pred p;\n\t"
            "mbarrier.try_wait.parity.acquire.cluster.shared::cta.b64 p, [%1], %2, 0x989680;\n\t"
            "selp.b32 %0, 1, 0, p;\n\t}"
            : "=r"(done) : "r"(addr), "r"(parity) : "memory");
    }
}
__device__ __forceinline__ void st_async_f32(unsigned raddr, float v,
                                             unsigned rmbar) {
    asm volatile(
        "st.async.shared::cluster.mbarrier::complete_tx::bytes.f32 [%0], %1, [%2];"
        :: "r"(raddr), "f"(v), "r"(rmbar) : "memory");
}
__device__ __forceinline__ void prefetch_l2(const void* p) {
    asm volatile("prefetch.global.L2 [%0];" :: "l"(p));
}

// ---------------- scratch (static device arrays; no runtime allocation) -----
__device__ float g_x   [TT * BB * EE];      // relu(embed), row = t*B + b
__device__ float g_xw  [TT * BB * GG];      // x @ W_x + b_lstm
__device__ float g_last[BB * EE];           // h at last valid timestep per row

// ---------------- kernel A: multi-hot embed (warp per visit, float4) --------
__global__ void __launch_bounds__(128, 8)
embed_kernel(const int* __restrict__ code,
             const float* __restrict__ aux,
             const float* __restrict__ Wlin,
             const float* __restrict__ blin) {
    int grp = threadIdx.x >> 5, lane = threadIdx.x & 31;
    int bt = blockIdx.x * 4 + grp;          // b*T + t
    int b = bt / TT, t = bt % TT;
    __shared__ int   codes[4][CC];
    __shared__ float flags[4][CC];
    __shared__ float auxs[4][DAUX];
    if (lane < CC)      codes[grp][lane]      = code[bt * CC + lane];
    if (lane + 32 < CC) codes[grp][lane + 32] = code[bt * CC + lane + 32];
    if (lane < DAUX)    auxs[grp][lane]       = aux[bt * DAUX + lane];
    __syncwarp();
    for (int c = lane; c < CC; c += 32) {
        int v = codes[grp][c];
        float f = (v > 0) ? 1.f : 0.f;
        for (int j = 0; j < c; j++)
            if (codes[grp][j] == v) f = 0.f;   // binary multi-hot: dedupe
        flags[grp][c] = f;
    }
    __syncwarp();
    float4 acc = *(const float4*)&blin[lane * 4];
    #pragma unroll 4
    for (int c = 0; c < CC; c++) {
        if (flags[grp][c] != 0.f) {            // uniform across warp
            float4 wv = *(const float4*)&Wlin[(codes[grp][c] - 1) * EE + lane * 4];
            acc.x += wv.x; acc.y += wv.y; acc.z += wv.z; acc.w += wv.w;
        }
    }
    #pragma unroll
    for (int k = 0; k < DAUX; k++) {
        float a = auxs[grp][k];
        float4 wv = *(const float4*)&Wlin[(NCODE + k) * EE + lane * 4];
        acc.x = fmaf(a, wv.x, acc.x); acc.y = fmaf(a, wv.y, acc.y);
        acc.z = fmaf(a, wv.z, acc.z); acc.w = fmaf(a, wv.w, acc.w);
    }
    float4 r;
    r.x = fmaxf(acc.x, 0.f); r.y = fmaxf(acc.y, 0.f);
    r.z = fmaxf(acc.z, 0.f); r.w = fmaxf(acc.w, 0.f);
    *(float4*)&g_x[(t * BB + b) * EE + lane * 4] = r;
}

// ---------------- kernel B: xw = x @ W_x + b_lstm  ([25600,128]@[128,512]) --
__global__ void __launch_bounds__(256, 1)
xw_kernel(const float* __restrict__ Wx, const float* __restrict__ blstm) {
    __shared__ float xs[64][68];   // [row][k]
    __shared__ float ws[64][68];   // [col][k]
    int tid = threadIdx.x;
    int row0 = blockIdx.x * 64, col0 = blockIdx.y * 64;
    int ty = tid >> 4, tx = tid & 15;   // rows: ty+16i, cols: tx+16j

    unsigned long long acc[4][4];
    #pragma unroll
    for (int i = 0; i < 4; i++)
        #pragma unroll
        for (int j = 0; j < 4; j++) acc[i][j] = 0ull;

    for (int kb = 0; kb < 128; kb += 64) {
        for (int i = tid; i < 64 * 16; i += 256) {
            int r = i >> 4, kq = i & 15;
            *(float4*)&xs[r][kq << 2] =
                *(const float4*)&g_x[(row0 + r) * EE + kb + (kq << 2)];
        }
        for (int i = tid; i < 64 * 64; i += 256) {
            int k = i >> 6, c = i & 63;
            ws[c][k] = Wx[(kb + k) * GG + col0 + c];
        }
        __syncthreads();
        #pragma unroll
        for (int k = 0; k < 64; k += 4) {
            ulonglong2 av[4], wv[4];
            #pragma unroll
            for (int i = 0; i < 4; i++)
                av[i] = *(const ulonglong2*)&xs[ty + 16 * i][k];
            #pragma unroll
            for (int j = 0; j < 4; j++)
                wv[j] = *(const ulonglong2*)&ws[tx + 16 * j][k];
            #pragma unroll
            for (int i = 0; i < 4; i++)
                #pragma unroll
                for (int j = 0; j < 4; j++) {
                    FMA2(acc[i][j], av[i].x, wv[j].x, acc[i][j]);
                    FMA2(acc[i][j], av[i].y, wv[j].y, acc[i][j]);
                }
        }
        __syncthreads();
    }
    #pragma unroll
    for (int i = 0; i < 4; i++) {
        int r = row0 + ty + 16 * i;
        #pragma unroll
        for (int j = 0; j < 4; j++) {
            int c = col0 + tx + 16 * j;
            g_xw[r * GG + c] = (plo(acc[i][j]) + phi(acc[i][j])) + blstm[c];
        }
    }
}

// ---------------- kernel C: cluster LSTM, st.async + mbarrier tx sync --------
// 32 clusters x 4 CTAs, 256 threads/CTA (R10 geometry). Changes vs R10:
// (1) xw(t+1) LDG issued right after the wait (max slack) + L2 prefetch t+2;
// (2) z_sm gate stride 40 -> conflict-free stores (bank = 8*gate+e8+8*wc).
#define CLUS 4

__global__ void __launch_bounds__(256, 1) __cluster_dims__(CLUS, 1, 1)
lstm_kernel(const float* __restrict__ Wh, const int* __restrict__ length) {
    __shared__ __align__(16) float h_sm[2][4][EE];   // double-buffered h
    __shared__ float z_sm[4][164];                   // [row][gate*40 + le]
    __shared__ __align__(8) unsigned long long mbar[2];

    int tid = threadIdx.x;                 // 256
    unsigned rank;
    asm("mov.u32 %0, %%cluster_ctarank;" : "=r"(rank));
    int b0 = (blockIdx.x >> 2) * 4;        // 4 batch rows per cluster
    int e0 = rank * 32;

    int lane = tid & 31, w = tid >> 5;
    int wr = w >> 2;                       // row pair 0/1
    int wc = w & 3;                        // e-subblock (8 wide)
    int r0 = 2 * wr, r1 = r0 + 1;          // local rows for FMA phase
    int gate = lane >> 3, e8 = lane & 7;
    int le = wc * 8 + e8;                  // local e in [0,32)
    int colg = gate * EE + e0 + le;        // z column in [0,512)
    int zc = gate * 40 + le;               // z_sm column (stride 40: bijective banks)

    // W_h column -> registers
    unsigned long long w_reg[64];
    #pragma unroll
    for (int j = 0; j < 64; j++)
        w_reg[j] = pack2(Wh[(2 * j) * GG + colg], Wh[(2 * j + 1) * GG + colg]);

    // zero own h buffer 0 (h_0 = 0); init + arm mbarriers
    for (int i = tid; i < 4 * EE; i += 256) (&h_sm[0][0][0])[i] = 0.f;
    unsigned mb0 = smem_u32(&mbar[0]);
    if (tid == 0) {
        mbar_init(mb0,     1);
        mbar_init(mb0 + 8, 1);
    }
    __syncthreads();
    if (tid == 0) {
        mbar_arm(mb0,     2048);           // phase 0 armed for first use
        mbar_arm(mb0 + 8, 2048);
    }

    // epilogue identity (tid < 128): slot = (row er, e ee)
    int er = tid >> 5, ee = tid & 31;      // er in [0,4) for tid<128
    int Lrow = (tid < 128) ? length[b0 + er] : 0;
    float cst = 0.f;

    // peer addresses (h buffers + mbarriers)
    unsigned hbase = smem_u32(&h_sm[0][0][0]);
    unsigned peerh[CLUS], peerm[CLUS];
    #pragma unroll
    for (int p = 0; p < CLUS; p++) {
        asm("mapa.shared::cluster.u32 %0, %1, %2;"
            : "=r"(peerh[p]) : "r"(hbase), "r"(p));
        asm("mapa.shared::cluster.u32 %0, %1, %2;"
            : "=r"(peerm[p]) : "r"(mb0), "r"(p));
    }

    // preload xw for t=0
    float xw0 = g_xw[(b0 + r0) * GG + colg];
    float xw1 = g_xw[(b0 + r1) * GG + colg];
    prefetch_l2(&g_xw[(1 * BB + b0 + r0) * GG + colg]);
    prefetch_l2(&g_xw[(1 * BB + b0 + r1) * GG + colg]);

    // inits + arms visible cluster-wide before any st.async arrives
    asm volatile("barrier.cluster.arrive.aligned;" ::: "memory");
    asm volatile("barrier.cluster.wait.aligned;" ::: "memory");

    int pc0 = 0, pc1 = 0;                  // per-mbarrier use counters

    for (int t = 0; t < TT; t++) {
        int buf = t & 1;

        if (t > 0) {
            unsigned off = (unsigned)buf * 8u;
            unsigned par = buf ? ((unsigned)pc1 & 1u) : ((unsigned)pc0 & 1u);
            mbar_wait(mb0 + off, par);
            if (buf) pc1++; else pc0++;
            if (tid == 0) mbar_arm(mb0 + off, 2048);   // re-arm next phase
        }

        // xw(t+1) load issued here: slack = FMA + sync + epilogue (~700 cyc);
        // L2 prefetch for t+2 turns the next load into an L2 hit.
        float nxw0 = 0.f, nxw1 = 0.f;
        if (t + 1 < TT) {
            nxw0 = g_xw[((t + 1) * BB + b0 + r0) * GG + colg];
            nxw1 = g_xw[((t + 1) * BB + b0 + r1) * GG + colg];
            if (t + 2 < TT) {
                prefetch_l2(&g_xw[((t + 2) * BB + b0 + r0) * GG + colg]);
                prefetch_l2(&g_xw[((t + 2) * BB + b0 + r1) * GG + colg]);
            }
        }

        unsigned long long a0 = 0ull, a1 = 0ull;
        const float* h0p = h_sm[buf][r0];
        const float* h1p = h_sm[buf][r1];
        #pragma unroll
        for (int k4 = 0; k4 < 32; k4++) {
            ulonglong2 hv0 = *(const ulonglong2*)(h0p + 4 * k4);
            ulonglong2 hv1 = *(const ulonglong2*)(h1p + 4 * k4);
            FMA2(a0, hv0.x, w_reg[2 * k4],     a0);
            FMA2(a1, hv1.x, w_reg[2 * k4],     a1);
            FMA2(a0, hv0.y, w_reg[2 * k4 + 1], a0);
            FMA2(a1, hv1.y, w_reg[2 * k4 + 1], a1);
        }
        z_sm[r0][zc] = xw0 + (plo(a0) + phi(a0));
        z_sm[r1][zc] = xw1 + (plo(a1) + phi(a1));
        __syncthreads();

        if (tid < 128) {
            float zi = z_sm[er][ee];
            float zf = z_sm[er][40 + ee];
            float zg = z_sm[er][80 + ee];
            float zo = z_sm[er][120 + ee];
            cst = fsig(zf) * cst + fsig(zi) * ftanh(zg);
            float h = fsig(zo) * ftanh(cst);

            // publish h_{t+1}: data store carries the completion signal
            unsigned hoff = (((unsigned)(buf ^ 1) * 4 + er) * EE + (e0 + ee)) * 4u;
            unsigned moff = (unsigned)(buf ^ 1) * 8u;
            #pragma unroll
            for (int i = 0; i < CLUS; i++) {
                int p = ((int)rank + i) & (CLUS - 1);
                st_async_f32(peerh[p] + hoff, h, peerm[p] + moff);
            }
            if (t + 1 == Lrow) g_last[(b0 + er) * EE + e0 + ee] = h;
        }

        xw0 = nxw0;
        xw1 = nxw1;
    }

    // drain: final stores (step 199) target mbar[0]; wait so no CTA exits
    // while peers' st.async into our smem are in flight
    mbar_wait(mb0, (unsigned)pc0 & 1u);
    asm volatile("barrier.cluster.arrive.aligned;" ::: "memory");
    asm volatile("barrier.cluster.wait.aligned;" ::: "memory");
}

// ---------------- kernel D: MLP head + L2-normalize --------------------------
__global__ void __launch_bounds__(256, 1)
head_kernel(const float* __restrict__ W0,
            const float* __restrict__ b0v,
            const float* __restrict__ W1,
            const float* __restrict__ b1v,
            float* __restrict__ out) {
    int b = blockIdx.x;             // 128
    int tid = threadIdx.x;          // 256
    __shared__ float hl[EE];
    __shared__ float m[HH];
    __shared__ float red[HH];
    if (tid < EE) hl[tid] = g_last[b * EE + tid];
    __syncthreads();
    float a0 = b0v[tid], a1 = 0.f, a2 = 0.f, a3 = 0.f;
    #pragma unroll
    for (int k = 0; k < EE; k += 4) {
        a0 = fmaf(hl[k],     W0[(k)     * HH + tid], a0);
        a1 = fmaf(hl[k + 1], W0[(k + 1) * HH + tid], a1);
        a2 = fmaf(hl[k + 2], W0[(k + 2) * HH + tid], a2);
        a3 = fmaf(hl[k + 3], W0[(k + 3) * HH + tid], a3);
    }
    m[tid] = fmaxf((a0 + a1) + (a2 + a3), 0.f);
    __syncthreads();
    float f0 = b1v[tid], f1 = 0.f, f2 = 0.f, f3 = 0.f;
    #pragma unroll
    for (int k = 0; k < HH; k += 4) {
        f0 = fmaf(m[k],     W1[(k)     * HH + tid], f0);
        f1 = fmaf(m[k + 1], W1[(k + 1) * HH + tid], f1);
        f2 = fmaf(m[k + 2], W1[(k + 2) * HH + tid], f2);
        f3 = fmaf(m[k + 3], W1[(k + 3) * HH + tid], f3);
    }
    float f = (f0 + f1) + (f2 + f3);
    red[tid] = f * f;
    __syncthreads();
    for (int s = 128; s > 0; s >>= 1) {
        if (tid < s) red[tid] += red[tid + s];
        __syncthreads();
    }
    out[b * HH + tid] = f / sqrtf(red[0]);
}

// ---------------- launch -----------------------------------------------------
extern "C" void kernel_launch(void* const* d_in, const int* in_sizes, int n_in,
                              void* d_out, int out_size) {
    const int*   code   = (const int*)  d_in[0];
    const float* aux    = (const float*)d_in[1];
    const int*   length = (const int*)  d_in[2];
    // d_in[3] = is_training (unused, inference)
    const float* Wlin   = (const float*)d_in[4];
    const float* blin   = (const float*)d_in[5];
    const float* Wx     = (const float*)d_in[6];
    const float* Wh     = (const float*)d_in[7];
    const float* blstm  = (const float*)d_in[8];
    const float* W0     = (const float*)d_in[9];
    const float* b0v    = (const float*)d_in[10];
    const float* W1     = (const float*)d_in[11];
    const float* b1v    = (const float*)d_in[12];
    float* out = (float*)d_out;

    embed_kernel<<<BB * TT / 4, 128>>>(code, aux, Wlin, blin);
    dim3 gb(TT * BB / 64, GG / 64);
    xw_kernel<<<gb, 256>>>(Wx, blstm);
    lstm_kernel<<<BB, 256>>>(Wh, length);   // 32 clusters x 4 CTAs
    head_kernel<<<BB, 256>>>(W0, b0v, W1, b1v, out);
}

// round 13
// speedup vs baseline: 1.0803x; 1.0329x over previous
#include <cuda_runtime.h>
#include <cuda_bf16.h>
#include <math.h>

#define BB   128     // batch
#define TT   200     // timesteps
#define CC   40      // codes per visit
#define NCODE 2000
#define DAUX 16
#define EE   128     // embedding dim
#define GG   512     // 4*E
#define HH   256     // mlp hidden

// packed f32x2 FMA (SASS FFMA2) — only reachable via PTX
#define FMA2(d, a, b, c) \
    asm("fma.rn.f32x2 %0, %1, %2, %3;" : "=l"(d) : "l"(a), "l"(b), "l"(c))

__device__ __forceinline__ float plo(unsigned long long v) {
    return __uint_as_float((unsigned)v);
}
__device__ __forceinline__ float phi(unsigned long long v) {
    return __uint_as_float((unsigned)(v >> 32));
}
__device__ __forceinline__ unsigned long long pack2(float lo, float hi) {
    return (unsigned long long)__float_as_uint(lo) |
           ((unsigned long long)__float_as_uint(hi) << 32);
}

__device__ __forceinline__ unsigned smem_u32(const void* p) {
    unsigned a;
    asm("{ .reg .u64 t; cvta.to.shared.u64 t, %1; cvt.u32.u64 %0, t; }"
        : "=r"(a) : "l"(p));
    return a;
}

// fast, saturation-safe gates (MUFU ex2 + rcp; abs err ~1e-7)
__device__ __forceinline__ float fsig(float x) {
    return __fdividef(1.f, 1.f + __expf(-x));
}
__device__ __forceinline__ float ftanh(float x) {
    return fmaf(2.f, fsig(2.f * x), -1.f);
}

// mbarrier + st.async helpers
__device__ __forceinline__ void mbar_init(unsigned addr, unsigned cnt) {
    asm volatile("mbarrier.init.shared.b64 [%0], %1;" :: "r"(addr), "r"(cnt)
                 : "memory");
}
__device__ __forceinline__ void mbar_arm(unsigned addr, unsigned tx) {
    asm volatile("mbarrier.arrive.expect_tx.shared.b64 _, [%0], %1;"
                 :: "r"(addr), "r"(tx) : "memory");
}
__device__ __forceinline__ void mbar_wait(unsigned addr, unsigned parity) {
    unsigned done;
    asm volatile(
        "{\n\t.reg .pred p;\n\t"
        "mbarrier.try_wait.parity.acquire.cluster.shared::cta.b64 p, [%1], %2;\n\t"
        "selp.b32 %0, 1, 0, p;\n\t}"
        : "=r"(done) : "r"(addr), "r"(parity) : "memory");
    while (!done) {
        asm volatile(
            "{\n\t.reg .pred p;\n\t"
            "mbarrier.try_wait.parity.acquire.cluster.shared::cta.b64 p, [%1], %2, 0x989680;\n\t"
            "selp.b32 %0, 1, 0, p;\n\t}"
            : "=r"(done) : "r"(addr), "r"(parity) : "memory");
    }
}
__device__ __forceinline__ void st_async_f32(unsigned raddr, float v,
                                             unsigned rmbar) {
    asm volatile(
        "st.async.shared::cluster.mbarrier::complete_tx::bytes.f32 [%0], %1, [%2];"
        :: "r"(raddr), "f"(v), "r"(rmbar) : "memory");
}
__device__ __forceinline__ void bar_named(int id) {
    asm volatile("bar.sync %0, 128;" :: "r"(id) : "memory");
}

// ---------------- scratch (static device arrays; no runtime allocation) -----
__device__ float g_x   [TT * BB * EE];      // relu(embed), row = t*B + b
__device__ float g_xw  [TT * BB * GG];      // x @ W_x + b_lstm
__device__ float g_last[BB * EE];           // h at last valid timestep per row

// ---------------- kernel A: multi-hot embed (warp per visit, float4) --------
__global__ void __launch_bounds__(128, 8)
embed_kernel(const int* __restrict__ code,
             const float* __restrict__ aux,
             const float* __restrict__ Wlin,
             const float* __restrict__ blin) {
    int grp = threadIdx.x >> 5, lane = threadIdx.x & 31;
    int bt = blockIdx.x * 4 + grp;          // b*T + t
    int b = bt / TT, t = bt % TT;
    __shared__ int   codes[4][CC];
    __shared__ float flags[4][CC];
    __shared__ float auxs[4][DAUX];
    if (lane < CC)      codes[grp][lane]      = code[bt * CC + lane];
    if (lane + 32 < CC) codes[grp][lane + 32] = code[bt * CC + lane + 32];
    if (lane < DAUX)    auxs[grp][lane]       = aux[bt * DAUX + lane];
    __syncwarp();
    for (int c = lane; c < CC; c += 32) {
        int v = codes[grp][c];
        float f = (v > 0) ? 1.f : 0.f;
        for (int j = 0; j < c; j++)
            if (codes[grp][j] == v) f = 0.f;   // binary multi-hot: dedupe
        flags[grp][c] = f;
    }
    __syncwarp();
    float4 acc = *(const float4*)&blin[lane * 4];
    #pragma unroll 4
    for (int c = 0; c < CC; c++) {
        if (flags[grp][c] != 0.f) {            // uniform across warp
            float4 wv = *(const float4*)&Wlin[(codes[grp][c] - 1) * EE + lane * 4];
            acc.x += wv.x; acc.y += wv.y; acc.z += wv.z; acc.w += wv.w;
        }
    }
    #pragma unroll
    for (int k = 0; k < DAUX; k++) {
        float a = auxs[grp][k];
        float4 wv = *(const float4*)&Wlin[(NCODE + k) * EE + lane * 4];
        acc.x = fmaf(a, wv.x, acc.x); acc.y = fmaf(a, wv.y, acc.y);
        acc.z = fmaf(a, wv.z, acc.z); acc.w = fmaf(a, wv.w, acc.w);
    }
    float4 r;
    r.x = fmaxf(acc.x, 0.f); r.y = fmaxf(acc.y, 0.f);
    r.z = fmaxf(acc.z, 0.f); r.w = fmaxf(acc.w, 0.f);
    *(float4*)&g_x[(t * BB + b) * EE + lane * 4] = r;
}

// ---------------- kernel B: xw = x @ W_x + b_lstm  ([25600,128]@[128,512]) --
__global__ void __launch_bounds__(256, 1)
xw_kernel(const float* __restrict__ Wx, const float* __restrict__ blstm) {
    __shared__ float xs[64][68];   // [row][k]
    __shared__ float ws[64][68];   // [col][k]
    int tid = threadIdx.x;
    int row0 = blockIdx.x * 64, col0 = blockIdx.y * 64;
    int ty = tid >> 4, tx = tid & 15;   // rows: ty+16i, cols: tx+16j

    unsigned long long acc[4][4];
    #pragma unroll
    for (int i = 0; i < 4; i++)
        #pragma unroll
        for (int j = 0; j < 4; j++) acc[i][j] = 0ull;

    for (int kb = 0; kb < 128; kb += 64) {
        for (int i = tid; i < 64 * 16; i += 256) {
            int r = i >> 4, kq = i & 15;
            *(float4*)&xs[r][kq << 2] =
                *(const float4*)&g_x[(row0 + r) * EE + kb + (kq << 2)];
        }
        for (int i = tid; i < 64 * 64; i += 256) {
            int k = i >> 6, c = i & 63;
            ws[c][k] = Wx[(kb + k) * GG + col0 + c];
        }
        __syncthreads();
        #pragma unroll
        for (int k = 0; k < 64; k += 4) {
            ulonglong2 av[4], wv[4];
            #pragma unroll
            for (int i = 0; i < 4; i++)
                av[i] = *(const ulonglong2*)&xs[ty + 16 * i][k];
            #pragma unroll
            for (int j = 0; j < 4; j++)
                wv[j] = *(const ulonglong2*)&ws[tx + 16 * j][k];
            #pragma unroll
            for (int i = 0; i < 4; i++)
                #pragma unroll
                for (int j = 0; j < 4; j++) {
                    FMA2(acc[i][j], av[i].x, wv[j].x, acc[i][j]);
                    FMA2(acc[i][j], av[i].y, wv[j].y, acc[i][j]);
                }
        }
        __syncthreads();
    }
    #pragma unroll
    for (int i = 0; i < 4; i++) {
        int r = row0 + ty + 16 * i;
        #pragma unroll
        for (int j = 0; j < 4; j++) {
            int c = col0 + tx + 16 * j;
            g_xw[r * GG + c] = (plo(acc[i][j]) + phi(acc[i][j])) + blstm[c];
        }
    }
}

// ---------------- kernel C: cluster LSTM, two desynchronized row-groups ------
// 32 clusters x 4 CTAs, 256 threads/CTA (R10 FMA geometry). Rows 0-1 (group A,
// warps 0-3) and rows 2-3 (group B, warps 4-7) are independent recurrence
// chains: each group has its own phase-alternating mbarriers (tx=1024 B) and
// named barrier. Each SMSP hosts one A-warp + one B-warp, so one group's
// propagate/wait window is hidden under the other group's FMA stream.
// Epilogue: group A on warps 0-1 (SMSP 0,1), group B on warps 6-7 (SMSP 2,3).
#define CLUS 4

__global__ void __launch_bounds__(256, 1) __cluster_dims__(CLUS, 1, 1)
lstm_kernel(const float* __restrict__ Wh, const int* __restrict__ length) {
    __shared__ __align__(16) float h_sm[2][4][EE];   // double-buffered h
    __shared__ float z_sm[4][132];                   // [row][gate*32 + le]
    __shared__ __align__(8) unsigned long long mbar[4];  // [A0,A1,B0,B1]

    int tid = threadIdx.x;                 // 256
    unsigned rank;
    asm("mov.u32 %0, %%cluster_ctarank;" : "=r"(rank));
    int b0 = (blockIdx.x >> 2) * 4;        // 4 batch rows per cluster
    int e0 = rank * 32;

    int lane = tid & 31, w = tid >> 5;
    int gid = w >> 2;                      // group: 0 = rows 0-1, 1 = rows 2-3
    int wc = w & 3;                        // e-subblock (8 wide)
    int r0 = 2 * gid, r1 = r0 + 1;         // this group's rows
    int gate = lane >> 3, e8 = lane & 7;
    int le = wc * 8 + e8;                  // local e in [0,32)
    int colg = gate * EE + e0 + le;        // z column in [0,512)
    int zc = gate * 32 + le;               // z_sm column

    // W_h column -> registers
    unsigned long long w_reg[64];
    #pragma unroll
    for (int j = 0; j < 64; j++)
        w_reg[j] = pack2(Wh[(2 * j) * GG + colg], Wh[(2 * j + 1) * GG + colg]);

    // zero own h buffer 0 (h_0 = 0); init + arm mbarriers
    for (int i = tid; i < 4 * EE; i += 256) (&h_sm[0][0][0])[i] = 0.f;
    unsigned mb0 = smem_u32(&mbar[0]);
    if (tid == 0) {
        mbar_init(mb0,      1);   // A phase 0
        mbar_init(mb0 + 8,  1);   // A phase 1
        mbar_init(mb0 + 16, 1);   // B phase 0
        mbar_init(mb0 + 24, 1);   // B phase 1
    }
    __syncthreads();
    if (tid == 0)   { mbar_arm(mb0,      1024); mbar_arm(mb0 + 8,  1024); }
    if (tid == 128) { mbar_arm(mb0 + 16, 1024); mbar_arm(mb0 + 24, 1024); }

    // epilogue identity: group A -> warps 0-1 (tid<64), group B -> warps 6-7
    // (tid>=192). Each active thread owns slot (row er, e ee).
    bool epi = (gid == 0) ? (tid < 64) : (tid >= 192);
    int er = (gid == 0) ? (tid >> 5) : (2 + ((tid - 192) >> 5));
    int ee = tid & 31;
    int Lrow = epi ? length[b0 + er] : 0;
    float cst = 0.f;

    // peer addresses (h buffers + mbarriers)
    unsigned hbase = smem_u32(&h_sm[0][0][0]);
    unsigned peerh[CLUS], peerm[CLUS];
    #pragma unroll
    for (int p = 0; p < CLUS; p++) {
        asm("mapa.shared::cluster.u32 %0, %1, %2;"
            : "=r"(peerh[p]) : "r"(hbase), "r"(p));
        asm("mapa.shared::cluster.u32 %0, %1, %2;"
            : "=r"(peerm[p]) : "r"(mb0), "r"(p));
    }

    // preload xw for t=0 (this group's rows)
    float xw0 = g_xw[(b0 + r0) * GG + colg];
    float xw1 = g_xw[(b0 + r1) * GG + colg];

    // inits + arms + h zero visible cluster-wide before any st.async arrives
    asm volatile("barrier.cluster.arrive.aligned;" ::: "memory");
    asm volatile("barrier.cluster.wait.aligned;" ::: "memory");

    unsigned gbase = (unsigned)gid * 16u;  // own group's mbarrier block
    int barid = 1 + gid;                   // named barrier id
    int pc0 = 0, pc1 = 0;                  // own group's phase-use counters

    for (int t = 0; t < TT; t++) {
        int buf = t & 1;

        if (t > 0) {
            unsigned off = gbase + (unsigned)buf * 8u;
            unsigned par = buf ? ((unsigned)pc1 & 1u) : ((unsigned)pc0 & 1u);
            mbar_wait(mb0 + off, par);
            if (buf) pc1++; else pc0++;
            if (tid == gid * 128) mbar_arm(mb0 + off, 1024);  // re-arm
        }

        unsigned long long a0 = 0ull, a1 = 0ull;
        const float* h0p = h_sm[buf][r0];
        const float* h1p = h_sm[buf][r1];
        #pragma unroll
        for (int k4 = 0; k4 < 32; k4++) {
            ulonglong2 hv0 = *(const ulonglong2*)(h0p + 4 * k4);
            ulonglong2 hv1 = *(const ulonglong2*)(h1p + 4 * k4);
            FMA2(a0, hv0.x, w_reg[2 * k4],     a0);
            FMA2(a1, hv1.x, w_reg[2 * k4],     a1);
            FMA2(a0, hv0.y, w_reg[2 * k4 + 1], a0);
            FMA2(a1, hv1.y, w_reg[2 * k4 + 1], a1);
        }
        z_sm[r0][zc] = xw0 + (plo(a0) + phi(a0));
        z_sm[r1][zc] = xw1 + (plo(a1) + phi(a1));
        bar_named(barid);                  // group-local: z complete

        if (epi) {
            float zi = z_sm[er][ee];
            float zf = z_sm[er][32 + ee];
            float zg = z_sm[er][64 + ee];
            float zo = z_sm[er][96 + ee];
            cst = fsig(zf) * cst + fsig(zi) * ftanh(zg);
            float h = fsig(zo) * ftanh(cst);

            // publish h_{t+1}: data store carries the completion signal
            unsigned hoff = (((unsigned)(buf ^ 1) * 4 + er) * EE + (e0 + ee)) * 4u;
            unsigned moff = gbase + (unsigned)(buf ^ 1) * 8u;
            #pragma unroll
            for (int i = 0; i < CLUS; i++) {
                int p = ((int)rank + i) & (CLUS - 1);
                st_async_f32(peerh[p] + hoff, h, peerm[p] + moff);
            }
            if (t + 1 == Lrow) g_last[(b0 + er) * EE + e0 + ee] = h;
        }

        // prefetch xw for t+1 (latency hidden under wait + next FMA)
        if (t + 1 < TT) {
            xw0 = g_xw[((t + 1) * BB + b0 + r0) * GG + colg];
            xw1 = g_xw[((t + 1) * BB + b0 + r1) * GG + colg];
        }
    }

    // drain own group's final phase (step 199 stores target phase 0), then
    // full cluster barrier so no CTA exits with peers' stores in flight.
    mbar_wait(mb0 + gbase, (unsigned)pc0 & 1u);
    asm volatile("barrier.cluster.arrive.aligned;" ::: "memory");
    asm volatile("barrier.cluster.wait.aligned;" ::: "memory");
}

// ---------------- kernel D: MLP head + L2-normalize --------------------------
__global__ void __launch_bounds__(256, 1)
head_kernel(const float* __restrict__ W0,
            const float* __restrict__ b0v,
            const float* __restrict__ W1,
            const float* __restrict__ b1v,
            float* __restrict__ out) {
    int b = blockIdx.x;             // 128
    int tid = threadIdx.x;          // 256
    __shared__ float hl[EE];
    __shared__ float m[HH];
    __shared__ float red[HH];
    if (tid < EE) hl[tid] = g_last[b * EE + tid];
    __syncthreads();
    float a0 = b0v[tid], a1 = 0.f, a2 = 0.f, a3 = 0.f;
    #pragma unroll
    for (int k = 0; k < EE; k += 4) {
        a0 = fmaf(hl[k],     W0[(k)     * HH + tid], a0);
        a1 = fmaf(hl[k + 1], W0[(k + 1) * HH + tid], a1);
        a2 = fmaf(hl[k + 2], W0[(k + 2) * HH + tid], a2);
        a3 = fmaf(hl[k + 3], W0[(k + 3) * HH + tid], a3);
    }
    m[tid] = fmaxf((a0 + a1) + (a2 + a3), 0.f);
    __syncthreads();
    float f0 = b1v[tid], f1 = 0.f, f2 = 0.f, f3 = 0.f;
    #pragma unroll
    for (int k = 0; k < HH; k += 4) {
        f0 = fmaf(m[k],     W1[(k)     * HH + tid], f0);
        f1 = fmaf(m[k + 1], W1[(k + 1) * HH + tid], f1);
        f2 = fmaf(m[k + 2], W1[(k + 2) * HH + tid], f2);
        f3 = fmaf(m[k + 3], W1[(k + 3) * HH + tid], f3);
    }
    float f = (f0 + f1) + (f2 + f3);
    red[tid] = f * f;
    __syncthreads();
    for (int s = 128; s > 0; s >>= 1) {
        if (tid < s) red[tid] += red[tid + s];
        __syncthreads();
    }
    out[b * HH + tid] = f / sqrtf(red[0]);
}

// ---------------- launch -----------------------------------------------------
extern "C" void kernel_launch(void* const* d_in, const int* in_sizes, int n_in,
                              void* d_out, int out_size) {
    const int*   code   = (const int*)  d_in[0];
    const float* aux    = (const float*)d_in[1];
    const int*   length = (const int*)  d_in[2];
    // d_in[3] = is_training (unused, inference)
    const float* Wlin   = (const float*)d_in[4];
    const float* blin   = (const float*)d_in[5];
    const float* Wx     = (const float*)d_in[6];
    const float* Wh     = (const float*)d_in[7];
    const float* blstm  = (const float*)d_in[8];
    const float* W0     = (const float*)d_in[9];
    const float* b0v    = (const float*)d_in[10];
    const float* W1     = (const float*)d_in[11];
    const float* b1v    = (const float*)d_in[12];
    float* out = (float*)d_out;

    embed_kernel<<<BB * TT / 4, 128>>>(code, aux, Wlin, blin);
    dim3 gb(TT * BB / 64, GG / 64);
    xw_kernel<<<gb, 256>>>(Wx, blstm);
    lstm_kernel<<<BB, 256>>>(Wh, length);   // 32 clusters x 4 CTAs
    head_kernel<<<BB, 256>>>(W0, b0v, W1, b1v, out);
}